// round 2
// baseline (speedup 1.0000x reference)
#include <cuda_runtime.h>

// ---------------- problem constants ----------------
#define T_DIM 4
#define B_DIM 16
#define C_DIM 128
#define E_DIM 256
#define H_DIM 32
#define W_DIM 32
#define HW_DIM (H_DIM * W_DIM)
#define TB_DIM (T_DIM * B_DIM)
#define BN_EPS 1e-5f
#define LIF_TAU 0.5f

// ---------------- device scratch (no allocations allowed) ----------------
__device__ float g_spk[(size_t)T_DIM * B_DIM * E_DIM * HW_DIM];  // spikes (67 MB)
__device__ float g_mem[(size_t)T_DIM * B_DIM * E_DIM * HW_DIM];  // pre-LIF (67 MB)
__device__ float g_w3f[E_DIM * C_DIM * 9];
__device__ float g_w4f[E_DIM * E_DIM * 9];
__device__ float g_wrf[E_DIM * C_DIM];
__device__ float g_bias[3 * E_DIM];   // [0]=conv3, [1]=conv4, [2]=residual

// ---------------- f32x2 packed-FMA helpers (sm_100+) ----------------
union F2U { float2 f2; unsigned long long u; };

__device__ __forceinline__ float2 fma2(float2 a, float2 b, float2 c) {
    F2U A, B, C, D;
    A.f2 = a; B.f2 = b; C.f2 = c;
    asm("fma.rn.f32x2 %0, %1, %2, %3;" : "=l"(D.u) : "l"(A.u), "l"(B.u), "l"(C.u));
    return D.f2;
}

__device__ __forceinline__ float2 lds2(const float* p) {
    return *reinterpret_cast<const float2*>(p);
}

// ---------------- BN folding (merged into 2 launches) ----------------
#define W3_N (E_DIM * C_DIM * 9)
#define W4_N (E_DIM * E_DIM * 9)
#define WR_N (E_DIM * C_DIM)

__global__ void fold_all_w(const float* __restrict__ w3, const float* __restrict__ g3, const float* __restrict__ v3,
                           const float* __restrict__ w4, const float* __restrict__ g4, const float* __restrict__ v4,
                           const float* __restrict__ wr, const float* __restrict__ gr, const float* __restrict__ vr,
                           float* __restrict__ w3f, float* __restrict__ w4f, float* __restrict__ wrf) {
    int i = blockIdx.x * blockDim.x + threadIdx.x;
    if (i < W3_N) {
        int e = i / (C_DIM * 9);
        w3f[i] = w3[i] * (g3[e] * rsqrtf(v3[e] + BN_EPS));
    } else if (i < W3_N + W4_N) {
        int j = i - W3_N;
        int e = j / (E_DIM * 9);
        w4f[j] = w4[j] * (g4[e] * rsqrtf(v4[e] + BN_EPS));
    } else if (i < W3_N + W4_N + WR_N) {
        int j = i - W3_N - W4_N;
        int e = j / C_DIM;
        wrf[j] = wr[j] * (gr[e] * rsqrtf(vr[e] + BN_EPS));
    }
}

__global__ void fold_all_b(const float* __restrict__ g3, const float* __restrict__ b3,
                           const float* __restrict__ m3, const float* __restrict__ v3,
                           const float* __restrict__ g4, const float* __restrict__ b4,
                           const float* __restrict__ m4, const float* __restrict__ v4,
                           const float* __restrict__ gr, const float* __restrict__ br,
                           const float* __restrict__ mr, const float* __restrict__ vr,
                           float* __restrict__ bf) {
    int e = threadIdx.x;
    if (e >= E_DIM) return;
    if (blockIdx.x == 0)      bf[e]             = b3[e] - m3[e] * (g3[e] * rsqrtf(v3[e] + BN_EPS));
    else if (blockIdx.x == 1) bf[E_DIM + e]     = b4[e] - m4[e] * (g4[e] * rsqrtf(v4[e] + BN_EPS));
    else                      bf[2 * E_DIM + e] = br[e] - mr[e] * (gr[e] * rsqrtf(vr[e] + BN_EPS));
}

// ---------------- LIF: sequential over T, hard reset (float4) ----------------
__global__ void lif_kernel(const float4* __restrict__ in,
                           float4* __restrict__ out, int npt4) {
    int i = blockIdx.x * blockDim.x + threadIdx.x;
    if (i >= npt4) return;
    float m0 = 0.f, m1 = 0.f, m2 = 0.f, m3 = 0.f;
#pragma unroll
    for (int t = 0; t < T_DIM; ++t) {
        float4 v = in[(size_t)t * npt4 + i];
        m0 = m0 * LIF_TAU + v.x;
        m1 = m1 * LIF_TAU + v.y;
        m2 = m2 * LIF_TAU + v.z;
        m3 = m3 * LIF_TAU + v.w;
        float4 s;
        s.x = (m0 >= 1.0f) ? 1.0f : 0.0f;  if (m0 >= 1.0f) m0 = 0.0f;
        s.y = (m1 >= 1.0f) ? 1.0f : 0.0f;  if (m1 >= 1.0f) m1 = 0.0f;
        s.z = (m2 >= 1.0f) ? 1.0f : 0.0f;  if (m2 >= 1.0f) m2 = 0.0f;
        s.w = (m3 >= 1.0f) ? 1.0f : 0.0f;  if (m3 >= 1.0f) m3 = 0.0f;
        out[(size_t)t * npt4 + i] = s;
    }
}

// ---------------- direct conv (+folded BN, optional residual add) ----------------
// Block: one image n, 32 output channels, 8 rows x 32 cols of pixels. 256 threads.
// Thread: 4 out-channels x 8 pixels (4 f32x2 pairs) -> 16 float2 accumulators.
template <int CIN, int KS, int CC, bool ADD>
__global__ void __launch_bounds__(256, 2)
conv_kernel(const float* __restrict__ in,
            const float* __restrict__ wf,
            const float* __restrict__ bias,
            const float* __restrict__ addend,
            float* __restrict__ out) {
    constexpr int EE      = 4;                  // out-channels per thread
    constexpr int E_BLK   = 8 * EE;             // 32 out-channels per block
    constexpr int ROWS    = 8;
    constexpr int IN_ROWS = ROWS + KS - 1;
    constexpr int IN_COLS = 34;
    constexpr int KK      = KS * KS;
    constexpr int IN_ELEMS = CC * IN_ROWS * IN_COLS;
    constexpr int W_ELEMS  = E_BLK * CC * KK;   // float2 count

    __shared__ __align__(16) float  s_in[IN_ELEMS];
    __shared__ __align__(16) float2 s_w[W_ELEMS];   // weights duplicated {w, w}

    const int n  = blockIdx.z;
    const int eo = blockIdx.y * E_BLK;
    const int r0 = blockIdx.x * ROWS;

    const int tid = threadIdx.x;
    const int wrp = tid >> 5;          // warp id: 4 e-values per warp (broadcast weights)
    const int pg  = tid & 31;
    const int rr  = pg >> 2;           // row within tile: 0..7
    const int x0  = (pg & 3) << 3;     // col base: 0,8,16,24

    float2 acc[EE][4];
#pragma unroll
    for (int i = 0; i < EE; ++i)
#pragma unroll
        for (int j = 0; j < 4; ++j) acc[i][j] = make_float2(0.0f, 0.0f);

    for (int c0 = 0; c0 < CIN; c0 += CC) {
        __syncthreads();
        // ---- stage input tile (halo + zero pad for KS==3) ----
        const float* inb = in + ((size_t)n * CIN + c0) * HW_DIM;
        for (int idx = tid; idx < IN_ELEMS; idx += 256) {
            int c   = idx / (IN_ROWS * IN_COLS);
            int rem = idx - c * (IN_ROWS * IN_COLS);
            int iy  = rem / IN_COLS;
            int ix  = rem - iy * IN_COLS;
            float val = 0.0f;
            if (KS == 3) {
                int gy = r0 + iy - 1;
                int gx = ix - 1;
                if ((unsigned)gy < (unsigned)H_DIM && (unsigned)gx < (unsigned)W_DIM)
                    val = inb[c * HW_DIM + gy * W_DIM + gx];
            } else {
                if (ix < W_DIM)
                    val = inb[c * HW_DIM + (r0 + iy) * W_DIM + ix];
            }
            s_in[idx] = val;
        }
        // ---- stage weights, duplicated into both f32x2 lanes ----
        for (int idx = tid; idx < W_ELEMS; idx += 256) {
            int e   = idx / (CC * KK);
            int rem = idx - e * (CC * KK);
            int c   = rem / KK;
            int k   = rem - c * KK;
            float wv = wf[((size_t)(eo + e) * CIN + (c0 + c)) * KK + k];
            s_w[idx] = make_float2(wv, wv);
        }
        __syncthreads();

        if (KS == 3) {
            for (int c = 0; c < CC; ++c) {
#pragma unroll
                for (int ky = 0; ky < 3; ++ky) {
                    const float* rowp = &s_in[(c * IN_ROWS + rr + ky) * IN_COLS + x0];
                    float2 q0 = lds2(rowp + 0);
                    float2 q1 = lds2(rowp + 2);
                    float2 q2 = lds2(rowp + 4);
                    float2 q3 = lds2(rowp + 6);
                    float2 q4 = lds2(rowp + 8);
                    float2 p1[4] = {make_float2(q0.y, q1.x),
                                    make_float2(q1.y, q2.x),
                                    make_float2(q2.y, q3.x),
                                    make_float2(q3.y, q4.x)};
                    float2 p0[4] = {q0, q1, q2, q3};
                    float2 p2[4] = {q1, q2, q3, q4};
                    const float2* wrow = &s_w[(wrp * EE) * (CC * KK) + c * KK + ky * 3];
#pragma unroll
                    for (int ee = 0; ee < EE; ++ee) {
                        float2 w0 = wrow[ee * CC * KK + 0];
                        float2 w1 = wrow[ee * CC * KK + 1];
                        float2 w2 = wrow[ee * CC * KK + 2];
#pragma unroll
                        for (int j = 0; j < 4; ++j) {
                            acc[ee][j] = fma2(w0, p0[j], acc[ee][j]);
                            acc[ee][j] = fma2(w1, p1[j], acc[ee][j]);
                            acc[ee][j] = fma2(w2, p2[j], acc[ee][j]);
                        }
                    }
                }
            }
        } else {  // KS == 1
            for (int c = 0; c < CC; ++c) {
                const float* rowp = &s_in[(c * IN_ROWS + rr) * IN_COLS + x0];
                float2 p[4] = {lds2(rowp + 0), lds2(rowp + 2),
                               lds2(rowp + 4), lds2(rowp + 6)};
                const float2* wp = &s_w[(wrp * EE) * CC + c];
#pragma unroll
                for (int ee = 0; ee < EE; ++ee) {
                    float2 w = wp[ee * CC];
#pragma unroll
                    for (int j = 0; j < 4; ++j)
                        acc[ee][j] = fma2(w, p[j], acc[ee][j]);
                }
            }
        }
    }

    // ---- epilogue: + bias (folded BN), optional + residual, store ----
#pragma unroll
    for (int ee = 0; ee < EE; ++ee) {
        int e = eo + wrp * EE + ee;
        float b = bias[e];
        size_t obase = ((size_t)n * E_DIM + e) * HW_DIM + (size_t)(r0 + rr) * W_DIM + x0;
#pragma unroll
        for (int j = 0; j < 4; ++j) {
            float lo = acc[ee][j].x + b;
            float hi = acc[ee][j].y + b;
            if (ADD) {
                lo += addend[obase + 2 * j];
                hi += addend[obase + 2 * j + 1];
            }
            out[obase + 2 * j]     = lo;
            out[obase + 2 * j + 1] = hi;
        }
    }
}

// ---------------- launch ----------------
extern "C" void kernel_launch(void* const* d_in, const int* in_sizes, int n_in,
                              void* d_out, int out_size) {
    const float* x  = (const float*)d_in[0];
    const float* w3 = (const float*)d_in[1];
    const float* g3 = (const float*)d_in[2];
    const float* b3 = (const float*)d_in[3];
    const float* m3 = (const float*)d_in[4];
    const float* v3 = (const float*)d_in[5];
    const float* w4 = (const float*)d_in[6];
    const float* g4 = (const float*)d_in[7];
    const float* b4 = (const float*)d_in[8];
    const float* m4 = (const float*)d_in[9];
    const float* v4 = (const float*)d_in[10];
    const float* wr = (const float*)d_in[11];
    const float* gr = (const float*)d_in[12];
    const float* br = (const float*)d_in[13];
    const float* mr = (const float*)d_in[14];
    const float* vr = (const float*)d_in[15];
    float* out = (float*)d_out;

    float *spk, *mem, *w3f, *w4f, *wrf, *bias;
    cudaGetSymbolAddress((void**)&spk,  g_spk);
    cudaGetSymbolAddress((void**)&mem,  g_mem);
    cudaGetSymbolAddress((void**)&w3f,  g_w3f);
    cudaGetSymbolAddress((void**)&w4f,  g_w4f);
    cudaGetSymbolAddress((void**)&wrf,  g_wrf);
    cudaGetSymbolAddress((void**)&bias, g_bias);

    // launch 1-2: fold BN into weights/bias
    fold_all_w<<<(W3_N + W4_N + WR_N + 255) / 256, 256>>>(w3, g3, v3, w4, g4, v4, wr, gr, vr,
                                                          w3f, w4f, wrf);
    fold_all_b<<<3, E_DIM>>>(g3, b3, m3, v3, g4, b4, m4, v4, gr, br, mr, vr, bias);

    const int npt_c4 = B_DIM * C_DIM * HW_DIM / 4;
    const int npt_e4 = B_DIM * E_DIM * HW_DIM / 4;
    dim3 cgrid(H_DIM / 8, E_DIM / 32, TB_DIM);  // (4, 8, 64)

    // launch 3: LIF on raw input -> spikes (C=128)
    lif_kernel<<<(npt_c4 + 255) / 256, 256>>>((const float4*)x, (float4*)spk, npt_c4);
    // launch 4: conv3 (128->256) + BN
    conv_kernel<C_DIM, 3, 8, false><<<cgrid, 256>>>(spk, w3f, bias, nullptr, mem);
    // launch 5: LIF -> spikes (E=256)
    lif_kernel<<<(npt_e4 + 255) / 256, 256>>>((const float4*)mem, (float4*)spk, npt_e4);
    // launch 6 (profiled by ncu -s 5): conv4 (256->256) + BN
    conv_kernel<E_DIM, 3, 8, false><<<cgrid, 256>>>(spk, w4f, bias + E_DIM, nullptr, mem);
    // launch 7: LIF -> spikes
    lif_kernel<<<(npt_e4 + 255) / 256, 256>>>((const float4*)mem, (float4*)spk, npt_e4);
    // launch 8: residual 1x1 conv on ORIGINAL x + BN + spikes -> d_out
    conv_kernel<C_DIM, 1, 16, true><<<cgrid, 256>>>(x, wrf, bias + 2 * E_DIM, spk, out);
}